// round 3
// baseline (speedup 1.0000x reference)
#include <cuda_runtime.h>

#define HH 8192
#define W  512
#define NPIX (HH * W)

// scratch (static __device__ arrays: allowed; no runtime allocation)
__device__ unsigned char g_mask[NPIX];   // bit0 = weak, bit1 = strong
__device__ int           g_nstat[NPIX];  // union-find parent
__device__ unsigned char g_flag[NPIX];   // root -> component contains strong

// ---------------------------------------------------------------------------
// K1: uint8 convert + Sobel + channel argmax + NMS + thresholds (fused, tiled)
// ---------------------------------------------------------------------------
__global__ void __launch_bounds__(256) k_grad(const float* __restrict__ in) {
    __shared__ float         simg[3][36][36];
    __shared__ float         smag[34][36];
    __shared__ unsigned char sdir[34][36];

    const int y0 = blockIdx.y * 32;
    const int x0 = blockIdx.x * 32;
    const int tid = threadIdx.x;

    // load 36x36 image halo per channel, edge-replicated on the full strip
    for (int i = tid; i < 36 * 36; i += 256) {
        int iy = i / 36, ix = i - iy * 36;
        int gy = y0 - 2 + iy; gy = gy < 0 ? 0 : (gy > HH - 1 ? HH - 1 : gy);
        int gx = x0 - 2 + ix; gx = gx < 0 ? 0 : (gx > W - 1 ? W - 1 : gx);
        int b = gy >> 9, h = gy & 511;
        int base = ((b * 3) << 18) + (h << 9) + gx;
        #pragma unroll
        for (int c = 0; c < 3; c++) {
            float v = in[base + (c << 18)];
            float f = floorf((v + 1.0f) * 0.5f * 255.0f);
            f = fminf(fmaxf(f, 0.0f), 255.0f);
            simg[c][iy][ix] = f;
        }
    }
    __syncthreads();

    // mag + quantized direction on 34x34 (zero outside the strip for NMS halo)
    for (int i = tid; i < 34 * 34; i += 256) {
        int my = i / 34, mx = i - my * 34;
        int yy = y0 - 1 + my, xx = x0 - 1 + mx;
        float mag = 0.0f;
        unsigned char dir = 0;
        if (yy >= 0 && yy < HH && xx >= 0 && xx < W) {
            float bx = 0.f, by = 0.f, bm = -1.0f;
            #pragma unroll
            for (int c = 0; c < 3; c++) {
                float i_mm = simg[c][my    ][mx    ], i_m0 = simg[c][my    ][mx + 1], i_mp = simg[c][my    ][mx + 2];
                float i_0m = simg[c][my + 1][mx    ],                                 i_0p = simg[c][my + 1][mx + 2];
                float i_pm = simg[c][my + 2][mx    ], i_p0 = simg[c][my + 2][mx + 1], i_pp = simg[c][my + 2][mx + 2];
                float gx = (i_mp + 2.0f * i_0p + i_pp) - (i_mm + 2.0f * i_0m + i_pm);
                float gy = (i_pm + 2.0f * i_p0 + i_pp) - (i_mm + 2.0f * i_m0 + i_mp);
                float m = fabsf(gx) + fabsf(gy);
                if (m > bm) { bm = m; bx = gx; by = gy; }   // first-max like argmax
            }
            mag = bm;
            const float TG22 = 0.4142135623730951f;
            float ax = fabsf(bx), ay = fabsf(by);
            if (ay < TG22 * ax)      dir = 0;                // horizontal
            else if (ay * TG22 > ax) dir = 1;                // vertical
            else dir = (bx * by >= 0.0f) ? 2 : 3;            // diagonals
        }
        smag[my][mx] = mag;
        sdir[my][mx] = dir;
    }
    __syncthreads();

    // NMS + thresholds for the interior 32x32; init CC state
    for (int i = tid; i < 32 * 32; i += 256) {
        int oy = i >> 5, ox = i & 31;
        float m = smag[oy + 1][ox + 1];
        unsigned char d = sdir[oy + 1][ox + 1];
        float n1, n2;
        switch (d) {
            case 0:  n1 = smag[oy + 1][ox    ]; n2 = smag[oy + 1][ox + 2]; break;
            case 1:  n1 = smag[oy    ][ox + 1]; n2 = smag[oy + 2][ox + 1]; break;
            case 2:  n1 = smag[oy    ][ox    ]; n2 = smag[oy + 2][ox + 2]; break;
            default: n1 = smag[oy    ][ox + 2]; n2 = smag[oy + 2][ox    ]; break;
        }
        bool keep = (m > n1) && (m >= n2);
        unsigned char msk = 0;
        if (keep && m > 100.0f) msk = 1;
        if (keep && m > 200.0f) msk = 3;
        int idx = (y0 + oy) * W + (x0 + ox);
        g_mask[idx]  = msk;
        g_nstat[idx] = idx;
        g_flag[idx]  = 0;
    }
}

// ---------------------------------------------------------------------------
// ECL-CC style lock-free union-find
// ---------------------------------------------------------------------------
__device__ __forceinline__ int find_repr(int idx) {
    int curr = g_nstat[idx];
    if (curr != idx) {
        int next, prev = idx;
        while (curr > (next = g_nstat[curr])) {
            g_nstat[prev] = next;   // path halving
            prev = curr;
            curr = next;
        }
    }
    return curr;
}

__device__ __forceinline__ void do_union(int a, int b) {
    int va = find_repr(a);
    int vb = find_repr(b);
    bool repeat;
    do {
        repeat = false;
        if (va != vb) {
            int ret;
            if (va < vb) {
                if ((ret = atomicCAS(&g_nstat[vb], vb, va)) != vb) { vb = ret; repeat = true; }
            } else {
                if ((ret = atomicCAS(&g_nstat[va], va, vb)) != va) { va = ret; repeat = true; }
            }
        }
    } while (repeat);
}

__global__ void __launch_bounds__(256) k_union() {
    int idx = blockIdx.x * 256 + threadIdx.x;
    if (idx >= NPIX) return;
    if (!(g_mask[idx] & 1)) return;
    int x = idx & (W - 1);
    if (x < W - 1 && (g_mask[idx + 1] & 1)) do_union(idx, idx + 1);
    int yd = idx + W;
    if (yd < NPIX) {
        if ((g_mask[yd] & 1))                do_union(idx, yd);
        if (x > 0     && (g_mask[yd - 1] & 1)) do_union(idx, yd - 1);
        if (x < W - 1 && (g_mask[yd + 1] & 1)) do_union(idx, yd + 1);
    }
}

// compress to root + flag roots whose component contains a strong pixel
__global__ void __launch_bounds__(256) k_flag() {
    int idx = blockIdx.x * 256 + threadIdx.x;
    if (idx >= NPIX) return;
    unsigned char m = g_mask[idx];
    if (!(m & 1)) return;
    int r = idx, p;
    while ((p = g_nstat[r]) != r) r = p;
    g_nstat[idx] = r;
    if (m & 2) g_flag[r] = 1;
}

// ---------------------------------------------------------------------------
// K4: emit (edges - 0.5)/0.5 = +/-1 into all 3 channels of (B,3,H,W)
// ---------------------------------------------------------------------------
__global__ void __launch_bounds__(256) k_out(float* __restrict__ out) {
    int idx = blockIdx.x * 256 + threadIdx.x;
    if (idx >= NPIX) return;
    float v = -1.0f;
    unsigned char m = g_mask[idx];
    if (m & 1) {
        if (g_flag[g_nstat[idx]]) v = 1.0f;
    }
    int y = idx >> 9, x = idx & 511;
    int b = y >> 9, h = y & 511;
    int o = ((b * 3) << 18) + (h << 9) + x;
    out[o]               = v;
    out[o + (1 << 18)]   = v;
    out[o + (2 << 18)]   = v;
}

extern "C" void kernel_launch(void* const* d_in, const int* in_sizes, int n_in,
                              void* d_out, int out_size) {
    const float* x = (const float*)d_in[0];
    float* out = (float*)d_out;
    dim3 g1(W / 32, HH / 32);
    k_grad<<<g1, 256>>>(x);
    int nb = NPIX / 256;
    k_union<<<nb, 256>>>();
    k_flag<<<nb, 256>>>();
    k_out<<<nb, 256>>>(out);
}

// round 4
// speedup vs baseline: 1.1647x; 1.1647x over previous
#include <cuda_runtime.h>

#define HH 8192
#define W  512
#define NPIX (HH * W)

// scratch (static __device__ arrays: allowed; no runtime allocation)
__device__ unsigned char g_mask[NPIX];   // bit0 = weak, bit1 = strong
__device__ int           g_nstat[NPIX];  // union-find parent (weak pixels only)
__device__ unsigned char g_flag[NPIX];   // root -> component contains strong

// ---------------------------------------------------------------------------
// generic lock-free union-find (works on global or shared parent arrays)
// invariant: parent index <= child index (min-attachment)
// ---------------------------------------------------------------------------
__device__ __forceinline__ int uf_find(int* p, int i) {
    int c = p[i];
    while (c != p[c]) c = p[c];
    return c;
}

__device__ __forceinline__ void uf_union(int* p, int a, int b) {
    int va = uf_find(p, a);
    int vb = uf_find(p, b);
    bool rep;
    do {
        rep = false;
        if (va != vb) {
            int ret;
            if (va < vb) {
                if ((ret = atomicCAS(&p[vb], vb, va)) != vb) { vb = ret; rep = true; }
            } else {
                if ((ret = atomicCAS(&p[va], va, vb)) != va) { va = ret; rep = true; }
            }
        }
    } while (rep);
}

// ---------------------------------------------------------------------------
// K1: uint8 convert + Sobel + channel argmax + NMS + thresholds + LOCAL CC
// ---------------------------------------------------------------------------
__global__ void __launch_bounds__(256) k_grad(const float* __restrict__ in) {
    __shared__ float         simg[3][36][36];
    __shared__ float         smag[34][36];
    __shared__ unsigned char sdir[34][36];
    __shared__ int           spar[1024];
    __shared__ unsigned char smsk[1024];

    const int y0 = blockIdx.y * 32;
    const int x0 = blockIdx.x * 32;
    const int tid = threadIdx.x;

    // load 36x36 image halo per channel, edge-replicated on the full strip
    for (int i = tid; i < 36 * 36; i += 256) {
        int iy = i / 36, ix = i - iy * 36;
        int gy = y0 - 2 + iy; gy = gy < 0 ? 0 : (gy > HH - 1 ? HH - 1 : gy);
        int gx = x0 - 2 + ix; gx = gx < 0 ? 0 : (gx > W - 1 ? W - 1 : gx);
        int b = gy >> 9, h = gy & 511;
        int base = ((b * 3) << 18) + (h << 9) + gx;
        #pragma unroll
        for (int c = 0; c < 3; c++) {
            float v = in[base + (c << 18)];
            float f = floorf((v + 1.0f) * 0.5f * 255.0f);
            f = fminf(fmaxf(f, 0.0f), 255.0f);
            simg[c][iy][ix] = f;
        }
    }
    __syncthreads();

    // mag + quantized direction on 34x34 (zero outside strip for NMS halo)
    for (int i = tid; i < 34 * 34; i += 256) {
        int my = i / 34, mx = i - my * 34;
        int yy = y0 - 1 + my, xx = x0 - 1 + mx;
        float mag = 0.0f;
        unsigned char dir = 0;
        if (yy >= 0 && yy < HH && xx >= 0 && xx < W) {
            float bx = 0.f, by = 0.f, bm = -1.0f;
            #pragma unroll
            for (int c = 0; c < 3; c++) {
                float i_mm = simg[c][my    ][mx    ], i_m0 = simg[c][my    ][mx + 1], i_mp = simg[c][my    ][mx + 2];
                float i_0m = simg[c][my + 1][mx    ],                                 i_0p = simg[c][my + 1][mx + 2];
                float i_pm = simg[c][my + 2][mx    ], i_p0 = simg[c][my + 2][mx + 1], i_pp = simg[c][my + 2][mx + 2];
                float gx = (i_mp + 2.0f * i_0p + i_pp) - (i_mm + 2.0f * i_0m + i_pm);
                float gy = (i_pm + 2.0f * i_p0 + i_pp) - (i_mm + 2.0f * i_m0 + i_mp);
                float m = fabsf(gx) + fabsf(gy);
                if (m > bm) { bm = m; bx = gx; by = gy; }   // first-max like argmax
            }
            mag = bm;
            const float TG22 = 0.4142135623730951f;
            float ax = fabsf(bx), ay = fabsf(by);
            if (ay < TG22 * ax)      dir = 0;                // horizontal
            else if (ay * TG22 > ax) dir = 1;                // vertical
            else dir = (bx * by >= 0.0f) ? 2 : 3;            // diagonals
        }
        smag[my][mx] = mag;
        sdir[my][mx] = dir;
    }
    __syncthreads();

    // NMS + thresholds on interior 32x32
    for (int i = tid; i < 1024; i += 256) {
        int oy = i >> 5, ox = i & 31;
        float m = smag[oy + 1][ox + 1];
        unsigned char d = sdir[oy + 1][ox + 1];
        float n1, n2;
        switch (d) {
            case 0:  n1 = smag[oy + 1][ox    ]; n2 = smag[oy + 1][ox + 2]; break;
            case 1:  n1 = smag[oy    ][ox + 1]; n2 = smag[oy + 2][ox + 1]; break;
            case 2:  n1 = smag[oy    ][ox    ]; n2 = smag[oy + 2][ox + 2]; break;
            default: n1 = smag[oy    ][ox + 2]; n2 = smag[oy + 2][ox    ]; break;
        }
        bool keep = (m > n1) && (m >= n2);
        unsigned char msk = 0;
        if (keep && m > 100.0f) msk = 1;
        if (keep && m > 200.0f) msk = 3;
        smsk[i] = msk;
        spar[i] = i;
    }
    __syncthreads();

    // local union-find inside the tile (smem atomics)
    for (int i = tid; i < 1024; i += 256) {
        if (smsk[i] & 1) {
            int ly = i >> 5, lx = i & 31;
            if (lx < 31 && (smsk[i + 1] & 1))  uf_union(spar, i, i + 1);
            if (ly < 31) {
                if ((smsk[i + 32] & 1))             uf_union(spar, i, i + 32);
                if (lx > 0  && (smsk[i + 31] & 1))  uf_union(spar, i, i + 31);
                if (lx < 31 && (smsk[i + 33] & 1))  uf_union(spar, i, i + 33);
            }
        }
    }
    __syncthreads();

    // write mask for all pixels; parents (rooted globally) + flag reset for weak only
    for (int i = tid; i < 1024; i += 256) {
        int oy = i >> 5, ox = i & 31;
        int gidx = (y0 + oy) * W + (x0 + ox);
        unsigned char msk = smsk[i];
        g_mask[gidx] = msk;
        if (msk & 1) {
            int r = spar[i];
            while (r != spar[r]) r = spar[r];
            g_nstat[gidx] = (y0 + (r >> 5)) * W + (x0 + (r & 31));
            g_flag[gidx] = 0;
        }
    }
}

// ---------------------------------------------------------------------------
// K2: cross-tile boundary unions only (global atomics)
// ---------------------------------------------------------------------------
#define NB_BOT (256 * 512)
#define NB_COL (8192 * 16)

__global__ void __launch_bounds__(256) k_union() {
    int t = blockIdx.x * 256 + threadIdx.x;
    if (t < NB_BOT) {
        // bottom row of each tile: S / SW / SE cross downward tile boundary
        int x = t & 511, ty = t >> 9;
        int y = ty * 32 + 31;
        if (y >= HH - 1) return;
        int idx = y * W + x;
        if (!(g_mask[idx] & 1)) return;
        int s = idx + W;
        if (g_mask[s] & 1)                   uf_union(g_nstat, idx, s);
        if (x > 0     && (g_mask[s - 1] & 1)) uf_union(g_nstat, idx, s - 1);
        if (x < W - 1 && (g_mask[s + 1] & 1)) uf_union(g_nstat, idx, s + 1);
    } else if (t < NB_BOT + NB_COL) {
        // right column of each tile: E / SE cross rightward tile boundary
        int t2 = t - NB_BOT;
        int y = t2 >> 4, tx = t2 & 15;
        int x = tx * 32 + 31;
        if (x >= W - 1) return;
        int idx = y * W + x;
        if (!(g_mask[idx] & 1)) return;
        if (g_mask[idx + 1] & 1) uf_union(g_nstat, idx, idx + 1);
        if ((y & 31) != 31 && y < HH - 1 && (g_mask[idx + W + 1] & 1))
            uf_union(g_nstat, idx, idx + W + 1);
    } else {
        // left column of each tile: SW crosses leftward tile boundary
        int t3 = t - NB_BOT - NB_COL;
        if (t3 >= NB_COL) return;
        int y = t3 >> 4, tx = t3 & 15;
        int x = tx * 32;
        if (x == 0 || (y & 31) == 31 || y >= HH - 1) return;
        int idx = y * W + x;
        if (!(g_mask[idx] & 1)) return;
        if (g_mask[idx + W - 1] & 1) uf_union(g_nstat, idx, idx + W - 1);
    }
}

// ---------------------------------------------------------------------------
// K3: compress to root + flag roots with a strong member (4 px/thread, MLP=4)
// ---------------------------------------------------------------------------
__global__ void __launch_bounds__(256) k_flag() {
    int t = blockIdx.x * 256 + threadIdx.x;
    int idx4 = t << 2;
    if (idx4 >= NPIX) return;
    unsigned int m4 = *(const unsigned int*)(g_mask + idx4);
    if ((m4 & 0x01010101u) == 0) return;
    #pragma unroll
    for (int j = 0; j < 4; j++) {
        unsigned int m = (m4 >> (8 * j)) & 0xFFu;
        if (!(m & 1)) continue;
        int idx = idx4 + j;
        int r = idx, p;
        while ((p = g_nstat[r]) != r) r = p;
        g_nstat[idx] = r;
        if (m & 2) g_flag[r] = 1;
    }
}

// ---------------------------------------------------------------------------
// K4: emit +/-1 into all 3 channels, 4 px/thread, float4 stores
// ---------------------------------------------------------------------------
__global__ void __launch_bounds__(256) k_out(float* __restrict__ out) {
    int t = blockIdx.x * 256 + threadIdx.x;
    int idx4 = t << 2;
    if (idx4 >= NPIX) return;
    unsigned int m4 = *(const unsigned int*)(g_mask + idx4);
    float4 v = make_float4(-1.f, -1.f, -1.f, -1.f);
    if (m4 & 0x01010101u) {
        int r0 = (m4 & 0x00000001u) ? g_nstat[idx4    ] : -1;
        int r1 = (m4 & 0x00000100u) ? g_nstat[idx4 + 1] : -1;
        int r2 = (m4 & 0x00010000u) ? g_nstat[idx4 + 2] : -1;
        int r3 = (m4 & 0x01000000u) ? g_nstat[idx4 + 3] : -1;
        if (r0 >= 0 && g_flag[r0]) v.x = 1.f;
        if (r1 >= 0 && g_flag[r1]) v.y = 1.f;
        if (r2 >= 0 && g_flag[r2]) v.z = 1.f;
        if (r3 >= 0 && g_flag[r3]) v.w = 1.f;
    }
    int y = idx4 >> 9, x = idx4 & 511;
    int b = y >> 9, h = y & 511;
    int o = ((b * 3) << 18) + (h << 9) + x;
    float4* o4 = (float4*)out;
    o4[o >> 2]               = v;
    o4[(o + (1 << 18)) >> 2] = v;
    o4[(o + (2 << 18)) >> 2] = v;
}

extern "C" void kernel_launch(void* const* d_in, const int* in_sizes, int n_in,
                              void* d_out, int out_size) {
    const float* x = (const float*)d_in[0];
    float* out = (float*)d_out;
    dim3 g1(W / 32, HH / 32);
    k_grad<<<g1, 256>>>(x);
    k_union<<<(NB_BOT + 2 * NB_COL) / 256, 256>>>();
    k_flag<<<NPIX / 1024, 256>>>();
    k_out<<<NPIX / 1024, 256>>>(out);
}

// round 5
// speedup vs baseline: 1.3621x; 1.1696x over previous
#include <cuda_runtime.h>

#define HH 8192
#define W  512
#define NPIX (HH * W)

// scratch (static __device__ arrays: allowed; no runtime allocation)
__device__ unsigned char g_mask[NPIX];   // bit0 = weak, bit1 = strong
__device__ int           g_nstat[NPIX];  // union-find parent (weak pixels only)
__device__ unsigned char g_flag[NPIX];   // root -> component contains strong

// ---------------------------------------------------------------------------
// ECL-CC find with path halving (invariant: parent <= child, min-attachment).
// Halving writes are racy-but-safe: they only shortcut monotone chains.
// ---------------------------------------------------------------------------
__device__ __forceinline__ int uf_repr(int* p, int i) {
    int curr = p[i];
    if (curr != i) {
        int prev = i, next;
        while (curr > (next = p[curr])) {
            p[prev] = next;      // path halving
            prev = curr;
            curr = next;
        }
    }
    return curr;
}

__device__ __forceinline__ void uf_union(int* p, int a, int b) {
    int va = uf_repr(p, a);
    int vb = uf_repr(p, b);
    bool rep;
    do {
        rep = false;
        if (va != vb) {
            int ret;
            if (va < vb) {
                if ((ret = atomicCAS(&p[vb], vb, va)) != vb) { vb = ret; rep = true; }
            } else {
                if ((ret = atomicCAS(&p[va], va, vb)) != va) { va = ret; rep = true; }
            }
        }
    } while (rep);
}

// ---------------------------------------------------------------------------
// K1: uint8 convert + Sobel + channel argmax + NMS + thresholds + LOCAL CC
// ---------------------------------------------------------------------------
__global__ void __launch_bounds__(256) k_grad(const float* __restrict__ in) {
    __shared__ float         simg[3][36][36];
    __shared__ float         smag[34][36];
    __shared__ unsigned char sdir[34][36];
    __shared__ int           spar[1024];
    __shared__ unsigned char smsk[1024];

    const int y0 = blockIdx.y * 32;
    const int x0 = blockIdx.x * 32;
    const int tid = threadIdx.x;

    // load 36x36 image halo per channel, edge-replicated on the full strip
    for (int i = tid; i < 36 * 36; i += 256) {
        int iy = i / 36, ix = i - iy * 36;
        int gy = y0 - 2 + iy; gy = gy < 0 ? 0 : (gy > HH - 1 ? HH - 1 : gy);
        int gx = x0 - 2 + ix; gx = gx < 0 ? 0 : (gx > W - 1 ? W - 1 : gx);
        int b = gy >> 9, h = gy & 511;
        int base = ((b * 3) << 18) + (h << 9) + gx;
        #pragma unroll
        for (int c = 0; c < 3; c++) {
            float v = in[base + (c << 18)];
            float f = floorf((v + 1.0f) * 0.5f * 255.0f);
            f = fminf(fmaxf(f, 0.0f), 255.0f);
            simg[c][iy][ix] = f;
        }
    }
    __syncthreads();

    // mag + quantized direction on 34x34 (zero outside strip for NMS halo)
    for (int i = tid; i < 34 * 34; i += 256) {
        int my = i / 34, mx = i - my * 34;
        int yy = y0 - 1 + my, xx = x0 - 1 + mx;
        float mag = 0.0f;
        unsigned char dir = 0;
        if (yy >= 0 && yy < HH && xx >= 0 && xx < W) {
            float bx = 0.f, by = 0.f, bm = -1.0f;
            #pragma unroll
            for (int c = 0; c < 3; c++) {
                float i_mm = simg[c][my    ][mx    ], i_m0 = simg[c][my    ][mx + 1], i_mp = simg[c][my    ][mx + 2];
                float i_0m = simg[c][my + 1][mx    ],                                 i_0p = simg[c][my + 1][mx + 2];
                float i_pm = simg[c][my + 2][mx    ], i_p0 = simg[c][my + 2][mx + 1], i_pp = simg[c][my + 2][mx + 2];
                float gx = (i_mp + 2.0f * i_0p + i_pp) - (i_mm + 2.0f * i_0m + i_pm);
                float gy = (i_pm + 2.0f * i_p0 + i_pp) - (i_mm + 2.0f * i_m0 + i_mp);
                float m = fabsf(gx) + fabsf(gy);
                if (m > bm) { bm = m; bx = gx; by = gy; }   // first-max like argmax
            }
            mag = bm;
            const float TG22 = 0.4142135623730951f;
            float ax = fabsf(bx), ay = fabsf(by);
            if (ay < TG22 * ax)      dir = 0;                // horizontal
            else if (ay * TG22 > ax) dir = 1;                // vertical
            else dir = (bx * by >= 0.0f) ? 2 : 3;            // diagonals
        }
        smag[my][mx] = mag;
        sdir[my][mx] = dir;
    }
    __syncthreads();

    // NMS + thresholds on interior 32x32
    for (int i = tid; i < 1024; i += 256) {
        int oy = i >> 5, ox = i & 31;
        float m = smag[oy + 1][ox + 1];
        unsigned char d = sdir[oy + 1][ox + 1];
        float n1, n2;
        switch (d) {
            case 0:  n1 = smag[oy + 1][ox    ]; n2 = smag[oy + 1][ox + 2]; break;
            case 1:  n1 = smag[oy    ][ox + 1]; n2 = smag[oy + 2][ox + 1]; break;
            case 2:  n1 = smag[oy    ][ox    ]; n2 = smag[oy + 2][ox + 2]; break;
            default: n1 = smag[oy    ][ox + 2]; n2 = smag[oy + 2][ox    ]; break;
        }
        bool keep = (m > n1) && (m >= n2);
        unsigned char msk = 0;
        if (keep && m > 100.0f) msk = 1;
        if (keep && m > 200.0f) msk = 3;
        smsk[i] = msk;
        spar[i] = i;
    }
    __syncthreads();

    // local union-find inside the tile (smem atomics, path-halving finds)
    for (int i = tid; i < 1024; i += 256) {
        if (smsk[i] & 1) {
            int ly = i >> 5, lx = i & 31;
            if (lx < 31 && (smsk[i + 1] & 1))  uf_union(spar, i, i + 1);
            if (ly < 31) {
                if ((smsk[i + 32] & 1))             uf_union(spar, i, i + 32);
                if (lx > 0  && (smsk[i + 31] & 1))  uf_union(spar, i, i + 31);
                if (lx < 31 && (smsk[i + 33] & 1))  uf_union(spar, i, i + 33);
            }
        }
    }
    __syncthreads();

    // write mask for all pixels; parents (rooted globally) + flag reset for weak only
    for (int i = tid; i < 1024; i += 256) {
        int oy = i >> 5, ox = i & 31;
        int gidx = (y0 + oy) * W + (x0 + ox);
        unsigned char msk = smsk[i];
        g_mask[gidx] = msk;
        if (msk & 1) {
            int r = uf_repr(spar, i);
            g_nstat[gidx] = (y0 + (r >> 5)) * W + (x0 + (r & 31));
            g_flag[gidx] = 0;
        }
    }
}

// ---------------------------------------------------------------------------
// K2: cross-tile boundary unions only (global atomics, halving finds)
// ---------------------------------------------------------------------------
#define NB_BOT (256 * 512)
#define NB_COL (8192 * 16)

__global__ void __launch_bounds__(256) k_union() {
    int t = blockIdx.x * 256 + threadIdx.x;
    if (t < NB_BOT) {
        // bottom row of each tile: S / SW / SE cross downward tile boundary
        int x = t & 511, ty = t >> 9;
        int y = ty * 32 + 31;
        if (y >= HH - 1) return;
        int idx = y * W + x;
        if (!(g_mask[idx] & 1)) return;
        int s = idx + W;
        if (g_mask[s] & 1)                    uf_union(g_nstat, idx, s);
        if (x > 0     && (g_mask[s - 1] & 1)) uf_union(g_nstat, idx, s - 1);
        if (x < W - 1 && (g_mask[s + 1] & 1)) uf_union(g_nstat, idx, s + 1);
    } else if (t < NB_BOT + NB_COL) {
        // right column of each tile: E / SE cross rightward tile boundary
        int t2 = t - NB_BOT;
        int y = t2 >> 4, tx = t2 & 15;
        int x = tx * 32 + 31;
        if (x >= W - 1) return;
        int idx = y * W + x;
        if (!(g_mask[idx] & 1)) return;
        if (g_mask[idx + 1] & 1) uf_union(g_nstat, idx, idx + 1);
        if ((y & 31) != 31 && y < HH - 1 && (g_mask[idx + W + 1] & 1))
            uf_union(g_nstat, idx, idx + W + 1);
    } else {
        // left column of each tile: SW crosses leftward tile boundary
        int t3 = t - NB_BOT - NB_COL;
        if (t3 >= NB_COL) return;
        int y = t3 >> 4, tx = t3 & 15;
        int x = tx * 32;
        if (x == 0 || (y & 31) == 31 || y >= HH - 1) return;
        int idx = y * W + x;
        if (!(g_mask[idx] & 1)) return;
        if (g_mask[idx + W - 1] & 1) uf_union(g_nstat, idx, idx + W - 1);
    }
}

// ---------------------------------------------------------------------------
// K3: compress to root (with halving => walkers cooperate) + flag strong roots
// ---------------------------------------------------------------------------
__global__ void __launch_bounds__(256) k_flag() {
    int t = blockIdx.x * 256 + threadIdx.x;
    int idx4 = t << 2;
    if (idx4 >= NPIX) return;
    unsigned int m4 = *(const unsigned int*)(g_mask + idx4);
    if ((m4 & 0x01010101u) == 0) return;
    #pragma unroll
    for (int j = 0; j < 4; j++) {
        unsigned int m = (m4 >> (8 * j)) & 0xFFu;
        if (!(m & 1)) continue;
        int idx = idx4 + j;
        int r = uf_repr(g_nstat, idx);
        g_nstat[idx] = r;
        if (m & 2) g_flag[r] = 1;
    }
}

// ---------------------------------------------------------------------------
// K4: emit +/-1 into all 3 channels, 8 px/thread; strong pixels skip lookups
// ---------------------------------------------------------------------------
__global__ void __launch_bounds__(256) k_out(float* __restrict__ out) {
    int t = blockIdx.x * 256 + threadIdx.x;
    int idx8 = t << 3;
    if (idx8 >= NPIX) return;
    uint2 m8 = *(const uint2*)(g_mask + idx8);
    unsigned int mw[2] = { m8.x, m8.y };
    float v[8];
    #pragma unroll
    for (int h = 0; h < 2; h++) {
        #pragma unroll
        for (int j = 0; j < 4; j++) {
            unsigned int m = (mw[h] >> (8 * j)) & 0xFFu;
            float val = -1.0f;
            if (m & 2) {
                val = 1.0f;                       // strong => always an edge
            } else if (m & 1) {
                if (g_flag[g_nstat[idx8 + h * 4 + j]]) val = 1.0f;
            }
            v[h * 4 + j] = val;
        }
    }
    int y = idx8 >> 9, x = idx8 & 511;
    int b = y >> 9, hh = y & 511;
    int o = ((b * 3) << 18) + (hh << 9) + x;
    float4 lo = make_float4(v[0], v[1], v[2], v[3]);
    float4 hi = make_float4(v[4], v[5], v[6], v[7]);
    float4* o4 = (float4*)out;
    int q = o >> 2;
    o4[q]                     = lo;  o4[q + 1]                     = hi;
    o4[q + (1 << 16)]         = lo;  o4[q + (1 << 16) + 1]         = hi;
    o4[q + (2 << 16)]         = lo;  o4[q + (2 << 16) + 1]         = hi;
}

extern "C" void kernel_launch(void* const* d_in, const int* in_sizes, int n_in,
                              void* d_out, int out_size) {
    const float* x = (const float*)d_in[0];
    float* out = (float*)d_out;
    dim3 g1(W / 32, HH / 32);
    k_grad<<<g1, 256>>>(x);
    k_union<<<(NB_BOT + 2 * NB_COL) / 256, 256>>>();
    k_flag<<<NPIX / 1024, 256>>>();
    k_out<<<NPIX / 2048, 256>>>(out);
}

// round 6
// speedup vs baseline: 1.4266x; 1.0473x over previous
#include <cuda_runtime.h>

#define HH 8192
#define W  512
#define NPIX (HH * W)

// scratch (static __device__ arrays: allowed; no runtime allocation)
__device__ unsigned char g_mask[NPIX];   // bit0 = weak, bit1 = strong
__device__ int           g_nstat[NPIX];  // union-find parent (weak pixels only)
__device__ unsigned char g_flag[NPIX];   // root -> component contains strong

// ---------------------------------------------------------------------------
// ECL-CC find with path halving (invariant: parent <= child, min-attachment).
// ---------------------------------------------------------------------------
__device__ __forceinline__ int uf_repr(int* p, int i) {
    int curr = p[i];
    if (curr != i) {
        int prev = i, next;
        while (curr > (next = p[curr])) {
            p[prev] = next;      // path halving
            prev = curr;
            curr = next;
        }
    }
    return curr;
}

__device__ __forceinline__ void uf_union(int* p, int a, int b) {
    int va = uf_repr(p, a);
    int vb = uf_repr(p, b);
    bool rep;
    do {
        rep = false;
        if (va != vb) {
            int ret;
            if (va < vb) {
                if ((ret = atomicCAS(&p[vb], vb, va)) != vb) { vb = ret; rep = true; }
            } else {
                if ((ret = atomicCAS(&p[va], va, vb)) != va) { va = ret; rep = true; }
            }
        }
    } while (rep);
}

// ---------------------------------------------------------------------------
// K1: uint8 convert (packed 3ch in one uint, 10-bit fields) + Sobel on packed
//     words + channel argmax + NMS + thresholds + LOCAL CC in smem
// All filter math is exact small-int => identical results to fp32 reference.
// ---------------------------------------------------------------------------
__global__ void __launch_bounds__(256) k_grad(const float* __restrict__ in) {
    __shared__ unsigned int  spack[36][36];  // r | g<<10 | b<<20
    __shared__ int           smag[34][36];
    __shared__ unsigned char sdir[34][36];
    __shared__ int           spar[1024];
    __shared__ unsigned char smsk[1024];

    const int y0 = blockIdx.y * 32;
    const int x0 = blockIdx.x * 32;
    const int tid = threadIdx.x;

    // load 36x36 halo, convert to uint8 (exact), pack 3 channels
    for (int i = tid; i < 36 * 36; i += 256) {
        int iy = i / 36, ix = i - iy * 36;
        int gy = y0 - 2 + iy; gy = gy < 0 ? 0 : (gy > HH - 1 ? HH - 1 : gy);
        int gx = x0 - 2 + ix; gx = gx < 0 ? 0 : (gx > W - 1 ? W - 1 : gx);
        int b = gy >> 9, h = gy & 511;
        int base = ((b * 3) << 18) + (h << 9) + gx;
        unsigned int pk = 0;
        #pragma unroll
        for (int c = 0; c < 3; c++) {
            float v = in[base + (c << 18)];
            float f = floorf((v + 1.0f) * 0.5f * 255.0f);
            f = fminf(fmaxf(f, 0.0f), 255.0f);
            pk |= ((unsigned int)(int)f) << (10 * c);
        }
        spack[iy][ix] = pk;
    }
    __syncthreads();

    // mag + quantized direction on 34x34 (packed Sobel: fields <= 1020 < 1024)
    for (int i = tid; i < 34 * 34; i += 256) {
        int my = i / 34, mx = i - my * 34;
        int yy = y0 - 1 + my, xx = x0 - 1 + mx;
        int mag = 0;
        unsigned char dir = 0;
        if (yy >= 0 && yy < HH && xx >= 0 && xx < W) {
            unsigned int nmm = spack[my    ][mx], nm0 = spack[my    ][mx + 1], nmp = spack[my    ][mx + 2];
            unsigned int n0m = spack[my + 1][mx],                              n0p = spack[my + 1][mx + 2];
            unsigned int npm = spack[my + 2][mx], np0 = spack[my + 2][mx + 1], npp = spack[my + 2][mx + 2];
            unsigned int Px = nmp + 2u * n0p + npp;   // right column  [1,2,1]
            unsigned int Mx = nmm + 2u * n0m + npm;   // left column   [1,2,1]
            unsigned int Py = npm + 2u * np0 + npp;   // bottom row    [1,2,1]
            unsigned int My = nmm + 2u * nm0 + nmp;   // top row       [1,2,1]
            int bm = -1, bgx = 0, bgy = 0;
            #pragma unroll
            for (int c = 0; c < 3; c++) {
                int sh = 10 * c;
                int gx = (int)((Px >> sh) & 1023u) - (int)((Mx >> sh) & 1023u);
                int gy = (int)((Py >> sh) & 1023u) - (int)((My >> sh) & 1023u);
                int m = abs(gx) + abs(gy);
                if (m > bm) { bm = m; bgx = gx; bgy = gy; }   // first-max
            }
            mag = bm;
            const float TG22 = 0.4142135623730951f;
            float fx = (float)bgx, fy = (float)bgy;           // exact conversions
            float ax = fabsf(fx), ay = fabsf(fy);
            if (ay < TG22 * ax)      dir = 0;                 // horizontal
            else if (ay * TG22 > ax) dir = 1;                 // vertical
            else dir = (bgx * bgy >= 0) ? 2 : 3;              // diagonals
        }
        smag[my][mx] = mag;
        sdir[my][mx] = dir;
    }
    __syncthreads();

    // NMS + thresholds on interior 32x32 (exact int compares)
    for (int i = tid; i < 1024; i += 256) {
        int oy = i >> 5, ox = i & 31;
        int m = smag[oy + 1][ox + 1];
        unsigned char d = sdir[oy + 1][ox + 1];
        int n1, n2;
        switch (d) {
            case 0:  n1 = smag[oy + 1][ox    ]; n2 = smag[oy + 1][ox + 2]; break;
            case 1:  n1 = smag[oy    ][ox + 1]; n2 = smag[oy + 2][ox + 1]; break;
            case 2:  n1 = smag[oy    ][ox    ]; n2 = smag[oy + 2][ox + 2]; break;
            default: n1 = smag[oy    ][ox + 2]; n2 = smag[oy + 2][ox    ]; break;
        }
        bool keep = (m > n1) && (m >= n2);
        unsigned char msk = 0;
        if (keep && m > 100) msk = 1;
        if (keep && m > 200) msk = 3;
        smsk[i] = msk;
        spar[i] = i;
    }
    __syncthreads();

    // local union-find inside the tile (smem atomics, path-halving finds)
    for (int i = tid; i < 1024; i += 256) {
        if (smsk[i] & 1) {
            int ly = i >> 5, lx = i & 31;
            if (lx < 31 && (smsk[i + 1] & 1))  uf_union(spar, i, i + 1);
            if (ly < 31) {
                if ((smsk[i + 32] & 1))             uf_union(spar, i, i + 32);
                if (lx > 0  && (smsk[i + 31] & 1))  uf_union(spar, i, i + 31);
                if (lx < 31 && (smsk[i + 33] & 1))  uf_union(spar, i, i + 33);
            }
        }
    }
    __syncthreads();

    // write mask for all pixels; rooted parents + flag reset for weak only
    for (int i = tid; i < 1024; i += 256) {
        int oy = i >> 5, ox = i & 31;
        int gidx = (y0 + oy) * W + (x0 + ox);
        unsigned char msk = smsk[i];
        g_mask[gidx] = msk;
        if (msk & 1) {
            int r = uf_repr(spar, i);
            g_nstat[gidx] = (y0 + (r >> 5)) * W + (x0 + (r & 31));
            g_flag[gidx] = 0;
        }
    }
}

// ---------------------------------------------------------------------------
// K2: cross-tile boundary unions only (global atomics, halving finds)
// ---------------------------------------------------------------------------
#define NB_BOT (256 * 512)
#define NB_COL (8192 * 16)

__global__ void __launch_bounds__(256) k_union() {
    int t = blockIdx.x * 256 + threadIdx.x;
    if (t < NB_BOT) {
        int x = t & 511, ty = t >> 9;
        int y = ty * 32 + 31;
        if (y >= HH - 1) return;
        int idx = y * W + x;
        if (!(g_mask[idx] & 1)) return;
        int s = idx + W;
        if (g_mask[s] & 1)                    uf_union(g_nstat, idx, s);
        if (x > 0     && (g_mask[s - 1] & 1)) uf_union(g_nstat, idx, s - 1);
        if (x < W - 1 && (g_mask[s + 1] & 1)) uf_union(g_nstat, idx, s + 1);
    } else if (t < NB_BOT + NB_COL) {
        int t2 = t - NB_BOT;
        int y = t2 >> 4, tx = t2 & 15;
        int x = tx * 32 + 31;
        if (x >= W - 1) return;
        int idx = y * W + x;
        if (!(g_mask[idx] & 1)) return;
        if (g_mask[idx + 1] & 1) uf_union(g_nstat, idx, idx + 1);
        if ((y & 31) != 31 && y < HH - 1 && (g_mask[idx + W + 1] & 1))
            uf_union(g_nstat, idx, idx + W + 1);
    } else {
        int t3 = t - NB_BOT - NB_COL;
        if (t3 >= NB_COL) return;
        int y = t3 >> 4, tx = t3 & 15;
        int x = tx * 32;
        if (x == 0 || (y & 31) == 31 || y >= HH - 1) return;
        int idx = y * W + x;
        if (!(g_mask[idx] & 1)) return;
        if (g_mask[idx + W - 1] & 1) uf_union(g_nstat, idx, idx + W - 1);
    }
}

// ---------------------------------------------------------------------------
// K3: compress to root + flag strong roots (batched parent loads, MLP=4)
// ---------------------------------------------------------------------------
__global__ void __launch_bounds__(256) k_flag() {
    int t = blockIdx.x * 256 + threadIdx.x;
    int idx4 = t << 2;
    if (idx4 >= NPIX) return;
    unsigned int m4 = *(const unsigned int*)(g_mask + idx4);
    if ((m4 & 0x01010101u) == 0) return;
    int par[4];
    #pragma unroll
    for (int j = 0; j < 4; j++)   // independent first-hop loads (MLP=4)
        par[j] = ((m4 >> (8 * j)) & 1u) ? g_nstat[idx4 + j] : -1;
    #pragma unroll
    for (int j = 0; j < 4; j++) {
        if (par[j] < 0) continue;
        int idx = idx4 + j;
        int r = par[j];
        if (r != idx) {
            int prev = idx, next;
            while (r > (next = g_nstat[r])) { g_nstat[prev] = next; prev = r; r = next; }
        }
        g_nstat[idx] = r;
        if ((m4 >> (8 * j)) & 2u) g_flag[r] = 1;
    }
}

// ---------------------------------------------------------------------------
// K4: emit +/-1, 8 px/thread; batched nstat loads then batched flag loads
// ---------------------------------------------------------------------------
__global__ void __launch_bounds__(256) k_out(float* __restrict__ out) {
    int t = blockIdx.x * 256 + threadIdx.x;
    int idx8 = t << 3;
    if (idx8 >= NPIX) return;
    uint2 m8 = *(const uint2*)(g_mask + idx8);
    unsigned int mw[2] = { m8.x, m8.y };
    unsigned int m[8];
    #pragma unroll
    for (int j = 0; j < 8; j++) m[j] = (mw[j >> 2] >> (8 * (j & 3))) & 0xFFu;

    int root[8];
    #pragma unroll
    for (int j = 0; j < 8; j++)   // wave 1: independent root loads (weak-only)
        root[j] = (m[j] == 1u) ? g_nstat[idx8 + j] : -1;
    unsigned char fl[8];
    #pragma unroll
    for (int j = 0; j < 8; j++)   // wave 2: independent flag loads
        fl[j] = (root[j] >= 0) ? g_flag[root[j]] : 0;

    float v[8];
    #pragma unroll
    for (int j = 0; j < 8; j++)
        v[j] = ((m[j] & 2u) || fl[j]) ? 1.0f : -1.0f;

    int y = idx8 >> 9, x = idx8 & 511;
    int b = y >> 9, hh = y & 511;
    int o = ((b * 3) << 18) + (hh << 9) + x;
    float4 lo = make_float4(v[0], v[1], v[2], v[3]);
    float4 hi = make_float4(v[4], v[5], v[6], v[7]);
    float4* o4 = (float4*)out;
    int q = o >> 2;
    o4[q]             = lo;  o4[q + 1]             = hi;
    o4[q + (1 << 16)] = lo;  o4[q + (1 << 16) + 1] = hi;
    o4[q + (2 << 16)] = lo;  o4[q + (2 << 16) + 1] = hi;
}

extern "C" void kernel_launch(void* const* d_in, const int* in_sizes, int n_in,
                              void* d_out, int out_size) {
    const float* x = (const float*)d_in[0];
    float* out = (float*)d_out;
    dim3 g1(W / 32, HH / 32);
    k_grad<<<g1, 256>>>(x);
    k_union<<<(NB_BOT + 2 * NB_COL) / 256, 256>>>();
    k_flag<<<NPIX / 1024, 256>>>();
    k_out<<<NPIX / 2048, 256>>>(out);
}

// round 7
// speedup vs baseline: 1.6377x; 1.1479x over previous
#include <cuda_runtime.h>

#define HH 8192
#define W  512
#define NPIX (HH * W)

// Union-find over priority keys: key = idx (strong) or idx + MOD (weak).
// Min-attachment => component root is strong iff component has a strong pixel.
__device__ unsigned char g_mask[NPIX];   // bit0 = weak, bit1 = strong
__device__ int           g_nstat[NPIX];  // parent KEY per weak pixel

// ---------------------------------------------------------------------------
// find with path halving on key-encoded parents. p indexed by (key & (MOD-1)).
// ---------------------------------------------------------------------------
template <int MOD>
__device__ __forceinline__ int uf_find(int* p, int key) {
    int curr = p[key & (MOD - 1)];
    if (curr != key) {
        int prev = key & (MOD - 1), next;
        while (curr > (next = p[curr & (MOD - 1)])) {
            p[prev] = next;                 // path halving
            prev = curr & (MOD - 1);
            curr = next;
        }
    }
    return curr;
}

template <int MOD>
__device__ __forceinline__ void uf_union(int* p, int ka, int kb) {
    int va = uf_find<MOD>(p, ka);
    int vb = uf_find<MOD>(p, kb);
    bool rep;
    do {
        rep = false;
        if (va != vb) {
            int ret;
            if (va < vb) {
                if ((ret = atomicCAS(&p[vb & (MOD - 1)], vb, va)) != vb) { vb = ret; rep = true; }
            } else {
                if ((ret = atomicCAS(&p[va & (MOD - 1)], va, vb)) != va) { va = ret; rep = true; }
            }
        }
    } while (rep);
}

// ---------------------------------------------------------------------------
// K1: uint8 convert (3ch packed, 10-bit fields) + Sobel + argmax + NMS +
//     thresholds + local CC (smem, key-encoded)
// ---------------------------------------------------------------------------
__global__ void __launch_bounds__(256) k_grad(const float* __restrict__ in) {
    __shared__ unsigned int  spack[36][36];
    __shared__ int           smag[34][36];
    __shared__ unsigned char sdir[34][36];
    __shared__ int           spar[1024];
    __shared__ unsigned char smsk[1024];

    const int y0 = blockIdx.y * 32;
    const int x0 = blockIdx.x * 32;
    const int tid = threadIdx.x;

    for (int i = tid; i < 36 * 36; i += 256) {
        int iy = i / 36, ix = i - iy * 36;
        int gy = y0 - 2 + iy; gy = gy < 0 ? 0 : (gy > HH - 1 ? HH - 1 : gy);
        int gx = x0 - 2 + ix; gx = gx < 0 ? 0 : (gx > W - 1 ? W - 1 : gx);
        int b = gy >> 9, h = gy & 511;
        int base = ((b * 3) << 18) + (h << 9) + gx;
        unsigned int pk = 0;
        #pragma unroll
        for (int c = 0; c < 3; c++) {
            float v = in[base + (c << 18)];
            float f = floorf((v + 1.0f) * 0.5f * 255.0f);
            f = fminf(fmaxf(f, 0.0f), 255.0f);
            pk |= ((unsigned int)(int)f) << (10 * c);
        }
        spack[iy][ix] = pk;
    }
    __syncthreads();

    for (int i = tid; i < 34 * 34; i += 256) {
        int my = i / 34, mx = i - my * 34;
        int yy = y0 - 1 + my, xx = x0 - 1 + mx;
        int mag = 0;
        unsigned char dir = 0;
        if (yy >= 0 && yy < HH && xx >= 0 && xx < W) {
            unsigned int nmm = spack[my    ][mx], nm0 = spack[my    ][mx + 1], nmp = spack[my    ][mx + 2];
            unsigned int n0m = spack[my + 1][mx],                              n0p = spack[my + 1][mx + 2];
            unsigned int npm = spack[my + 2][mx], np0 = spack[my + 2][mx + 1], npp = spack[my + 2][mx + 2];
            unsigned int Px = nmp + 2u * n0p + npp;
            unsigned int Mx = nmm + 2u * n0m + npm;
            unsigned int Py = npm + 2u * np0 + npp;
            unsigned int My = nmm + 2u * nm0 + nmp;
            int bm = -1, bgx = 0, bgy = 0;
            #pragma unroll
            for (int c = 0; c < 3; c++) {
                int sh = 10 * c;
                int gx = (int)((Px >> sh) & 1023u) - (int)((Mx >> sh) & 1023u);
                int gy = (int)((Py >> sh) & 1023u) - (int)((My >> sh) & 1023u);
                int m = abs(gx) + abs(gy);
                if (m > bm) { bm = m; bgx = gx; bgy = gy; }
            }
            mag = bm;
            const float TG22 = 0.4142135623730951f;
            float fx = (float)bgx, fy = (float)bgy;
            float ax = fabsf(fx), ay = fabsf(fy);
            if (ay < TG22 * ax)      dir = 0;
            else if (ay * TG22 > ax) dir = 1;
            else dir = (bgx * bgy >= 0) ? 2 : 3;
        }
        smag[my][mx] = mag;
        sdir[my][mx] = dir;
    }
    __syncthreads();

    for (int i = tid; i < 1024; i += 256) {
        int oy = i >> 5, ox = i & 31;
        int m = smag[oy + 1][ox + 1];
        unsigned char d = sdir[oy + 1][ox + 1];
        int n1, n2;
        switch (d) {
            case 0:  n1 = smag[oy + 1][ox    ]; n2 = smag[oy + 1][ox + 2]; break;
            case 1:  n1 = smag[oy    ][ox + 1]; n2 = smag[oy + 2][ox + 1]; break;
            case 2:  n1 = smag[oy    ][ox    ]; n2 = smag[oy + 2][ox + 2]; break;
            default: n1 = smag[oy    ][ox + 2]; n2 = smag[oy + 2][ox    ]; break;
        }
        bool keep = (m > n1) && (m >= n2);
        unsigned char msk = 0;
        if (keep && m > 100) msk = 1;
        if (keep && m > 200) msk = 3;
        smsk[i] = msk;
        spar[i] = (msk & 2) ? i : i + 1024;   // key: strong gets low range
    }
    __syncthreads();

    // local union-find (smem atomics, key-encoded)
    for (int i = tid; i < 1024; i += 256) {
        if (smsk[i] & 1) {
            int ki = spar[i];   // still own key here? may have been halved; recompute:
            ki = (smsk[i] & 2) ? i : i + 1024;
            int ly = i >> 5, lx = i & 31;
            if (lx < 31 && (smsk[i + 1] & 1))
                uf_union<1024>(spar, ki, (smsk[i + 1] & 2) ? i + 1 : i + 1025);
            if (ly < 31) {
                if (smsk[i + 32] & 1)
                    uf_union<1024>(spar, ki, (smsk[i + 32] & 2) ? i + 32 : i + 32 + 1024);
                if (lx > 0 && (smsk[i + 31] & 1))
                    uf_union<1024>(spar, ki, (smsk[i + 31] & 2) ? i + 31 : i + 31 + 1024);
                if (lx < 31 && (smsk[i + 33] & 1))
                    uf_union<1024>(spar, ki, (smsk[i + 33] & 2) ? i + 33 : i + 33 + 1024);
            }
        }
    }
    __syncthreads();

    // write mask; rooted global parent keys for weak pixels
    for (int i = tid; i < 1024; i += 256) {
        int oy = i >> 5, ox = i & 31;
        int gidx = (y0 + oy) * W + (x0 + ox);
        unsigned char msk = smsk[i];
        g_mask[gidx] = msk;
        if (msk & 1) {
            int lkey = (msk & 2) ? i : i + 1024;
            int r = uf_find<1024>(spar, lkey);
            int li = r & 1023;
            int gr = (y0 + (li >> 5)) * W + (x0 + (li & 31));
            g_nstat[gidx] = (r < 1024) ? gr : gr + NPIX;   // preserve strongness
        }
    }
}

// ---------------------------------------------------------------------------
// K2: cross-tile boundary unions (global atomics, key-encoded)
// ---------------------------------------------------------------------------
#define NB_BOT (256 * 512)
#define NB_COL (8192 * 16)

__device__ __forceinline__ int gkey(int idx, unsigned char m) {
    return (m & 2) ? idx : idx + NPIX;
}

__global__ void __launch_bounds__(256) k_union() {
    int t = blockIdx.x * 256 + threadIdx.x;
    if (t < NB_BOT) {
        int x = t & 511, ty = t >> 9;
        int y = ty * 32 + 31;
        if (y >= HH - 1) return;
        int idx = y * W + x;
        unsigned char mi = g_mask[idx];
        if (!(mi & 1)) return;
        int ki = gkey(idx, mi);
        int s = idx + W;
        unsigned char ms = g_mask[s];
        if (ms & 1) uf_union<NPIX>(g_nstat, ki, gkey(s, ms));
        if (x > 0) {
            unsigned char mw = g_mask[s - 1];
            if (mw & 1) uf_union<NPIX>(g_nstat, ki, gkey(s - 1, mw));
        }
        if (x < W - 1) {
            unsigned char me = g_mask[s + 1];
            if (me & 1) uf_union<NPIX>(g_nstat, ki, gkey(s + 1, me));
        }
    } else if (t < NB_BOT + NB_COL) {
        int t2 = t - NB_BOT;
        int y = t2 >> 4, tx = t2 & 15;
        int x = tx * 32 + 31;
        if (x >= W - 1) return;
        int idx = y * W + x;
        unsigned char mi = g_mask[idx];
        if (!(mi & 1)) return;
        int ki = gkey(idx, mi);
        unsigned char me = g_mask[idx + 1];
        if (me & 1) uf_union<NPIX>(g_nstat, ki, gkey(idx + 1, me));
        if ((y & 31) != 31 && y < HH - 1) {
            unsigned char md = g_mask[idx + W + 1];
            if (md & 1) uf_union<NPIX>(g_nstat, ki, gkey(idx + W + 1, md));
        }
    } else {
        int t3 = t - NB_BOT - NB_COL;
        if (t3 >= NB_COL) return;
        int y = t3 >> 4, tx = t3 & 15;
        int x = tx * 32;
        if (x == 0 || (y & 31) == 31 || y >= HH - 1) return;
        int idx = y * W + x;
        unsigned char mi = g_mask[idx];
        if (!(mi & 1)) return;
        unsigned char md = g_mask[idx + W - 1];
        if (md & 1) uf_union<NPIX>(g_nstat, idx + ((mi & 2) ? 0 : NPIX), gkey(idx + W - 1, md));
    }
}

// ---------------------------------------------------------------------------
// K3 (was K4): find root per weak pixel; edge iff root key < NPIX (strong root)
// ---------------------------------------------------------------------------
__global__ void __launch_bounds__(256) k_out(float* __restrict__ out) {
    int t = blockIdx.x * 256 + threadIdx.x;
    int idx8 = t << 3;
    if (idx8 >= NPIX) return;
    uint2 m8 = *(const uint2*)(g_mask + idx8);
    unsigned int mw[2] = { m8.x, m8.y };
    unsigned int m[8];
    #pragma unroll
    for (int j = 0; j < 8; j++) m[j] = (mw[j >> 2] >> (8 * (j & 3))) & 0xFFu;

    // wave 1: independent first-hop parent loads (weak-only pixels)
    int par[8];
    #pragma unroll
    for (int j = 0; j < 8; j++)
        par[j] = (m[j] == 1u) ? g_nstat[idx8 + j] : -1;

    float v[8];
    #pragma unroll
    for (int j = 0; j < 8; j++) {
        float val = -1.0f;
        if (m[j] & 2u) {
            val = 1.0f;                         // strong => edge
        } else if (m[j] & 1u) {
            int idx = idx8 + j;
            int curr = par[j];
            int key = idx + NPIX;
            if (curr != key) {
                int prev = idx, next;
                while (curr > (next = g_nstat[curr & (NPIX - 1)])) {
                    g_nstat[prev] = next;       // halving: cooperate with peers
                    prev = curr & (NPIX - 1);
                    curr = next;
                }
            }
            if (curr < NPIX) val = 1.0f;        // strong-rooted component
        }
        v[j] = val;
    }

    int y = idx8 >> 9, x = idx8 & 511;
    int b = y >> 9, hh = y & 511;
    int o = ((b * 3) << 18) + (hh << 9) + x;
    float4 lo = make_float4(v[0], v[1], v[2], v[3]);
    float4 hi = make_float4(v[4], v[5], v[6], v[7]);
    float4* o4 = (float4*)out;
    int q = o >> 2;
    o4[q]             = lo;  o4[q + 1]             = hi;
    o4[q + (1 << 16)] = lo;  o4[q + (1 << 16) + 1] = hi;
    o4[q + (2 << 16)] = lo;  o4[q + (2 << 16) + 1] = hi;
}

extern "C" void kernel_launch(void* const* d_in, const int* in_sizes, int n_in,
                              void* d_out, int out_size) {
    const float* x = (const float*)d_in[0];
    float* out = (float*)d_out;
    dim3 g1(W / 32, HH / 32);
    k_grad<<<g1, 256>>>(x);
    k_union<<<(NB_BOT + 2 * NB_COL) / 256, 256>>>();
    k_out<<<NPIX / 2048, 256>>>(out);
}